// round 1
// baseline (speedup 1.0000x reference)
#include <cuda_runtime.h>
#include <cstdint>

#define N_ROWS 8192
#define D_IN   256
#define H_DIM  512
#define K_PROT 64
#define TYPES  17
#define SLOTS  (K_PROT*TYPES)
#define CLUSTER 8
#define ROWS_MAX 128
#define KLF (1.0f/1.05f)
#define ITERS 50

// ---------------- scratch (static device globals; no allocs allowed) -------
__device__ float g_h[N_ROWS*H_DIM];   // 16 MB
__device__ float g_hh[N_ROWS];
__device__ float g_pp[K_PROT];
__device__ float g_M[N_ROWS*K_PROT];  // 2 MB : -d2/tau
__device__ int   g_perm[N_ROWS];
__device__ int   g_offs[TYPES];
__device__ int   g_cnt[TYPES];
__device__ float g_u[N_ROWS];
__device__ float g_v[SLOTS];          // [t*64 + k]

// ---------------- GEMM1: h = selu(emb @ W1 + b1) ---------------------------
__global__ void gemm1_selu(const float* __restrict__ A,  // [8192,256]
                           const float* __restrict__ B,  // [256,512]
                           const float* __restrict__ bias)
{
    __shared__ float As[16][68];
    __shared__ float Bs[16][68];
    int tid = threadIdx.x;
    int tx = tid & 15, ty = tid >> 4;
    int row0 = blockIdx.y * 64, col0 = blockIdx.x * 64;
    float acc[4][4];
#pragma unroll
    for (int i = 0; i < 4; i++)
#pragma unroll
        for (int j = 0; j < 4; j++) acc[i][j] = 0.f;

    int ar = tid >> 2, ac = (tid & 3) * 4;
    int br = tid >> 4, bc = (tid & 15) * 4;

    for (int k0 = 0; k0 < D_IN; k0 += 16) {
        float4 a4 = *(const float4*)(A + (size_t)(row0 + ar) * D_IN + k0 + ac);
        As[ac + 0][ar] = a4.x; As[ac + 1][ar] = a4.y;
        As[ac + 2][ar] = a4.z; As[ac + 3][ar] = a4.w;
        *(float4*)&Bs[br][bc] =
            *(const float4*)(B + (size_t)(k0 + br) * H_DIM + col0 + bc);
        __syncthreads();
#pragma unroll
        for (int kk = 0; kk < 16; kk++) {
            float4 a = *(const float4*)&As[kk][ty * 4];
            float4 b = *(const float4*)&Bs[kk][tx * 4];
            acc[0][0] += a.x * b.x; acc[0][1] += a.x * b.y;
            acc[0][2] += a.x * b.z; acc[0][3] += a.x * b.w;
            acc[1][0] += a.y * b.x; acc[1][1] += a.y * b.y;
            acc[1][2] += a.y * b.z; acc[1][3] += a.y * b.w;
            acc[2][0] += a.z * b.x; acc[2][1] += a.z * b.y;
            acc[2][2] += a.z * b.z; acc[2][3] += a.z * b.w;
            acc[3][0] += a.w * b.x; acc[3][1] += a.w * b.y;
            acc[3][2] += a.w * b.z; acc[3][3] += a.w * b.w;
        }
        __syncthreads();
    }
    const float LAM = 1.0507009873554805f, AL = 1.6732632423543772f;
#pragma unroll
    for (int i = 0; i < 4; i++) {
#pragma unroll
        for (int j = 0; j < 4; j++) {
            float x = acc[i][j] + bias[col0 + tx * 4 + j];
            float y = (x > 0.f) ? LAM * x : LAM * AL * expm1f(x);
            g_h[(size_t)(row0 + ty * 4 + i) * H_DIM + col0 + tx * 4 + j] = y;
        }
    }
}

// ---------------- row norms of h and prototypes -----------------------------
__global__ void rownorms(const float* __restrict__ P)
{
    int warp = threadIdx.x >> 5, lane = threadIdx.x & 31;
    int b = blockIdx.x;
    const float* src; float* dst;
    if (b < 1024) {
        int row = b * 8 + warp;
        src = g_h + (size_t)row * H_DIM; dst = g_hh + row;
    } else {
        int row = (b - 1024) * 8 + warp;
        if (row >= K_PROT) return;
        src = P + (size_t)row * H_DIM; dst = g_pp + row;
    }
    float s = 0.f;
    for (int c = lane * 4; c < H_DIM; c += 128) {
        float4 v = *(const float4*)(src + c);
        s += v.x * v.x + v.y * v.y + v.z * v.z + v.w * v.w;
    }
#pragma unroll
    for (int o = 16; o; o >>= 1) s += __shfl_xor_sync(0xffffffffu, s, o);
    if (lane == 0) *dst = s;
}

// ---------------- GEMM2: M = -max(d2,0)/tau --------------------------------
__global__ void gemm2_M(const float* __restrict__ Pm)  // [64,512]
{
    __shared__ float As[16][68];
    __shared__ float Bs[16][68];
    int tid = threadIdx.x;
    int tx = tid & 15, ty = tid >> 4;
    int row0 = blockIdx.x * 64;
    float acc[4][4];
#pragma unroll
    for (int i = 0; i < 4; i++)
#pragma unroll
        for (int j = 0; j < 4; j++) acc[i][j] = 0.f;

    int ar = tid >> 2, ac = (tid & 3) * 4;
    int pc = tid >> 2, pk = (tid & 3) * 4;

    for (int k0 = 0; k0 < H_DIM; k0 += 16) {
        float4 a4 = *(const float4*)(g_h + (size_t)(row0 + ar) * H_DIM + k0 + ac);
        As[ac + 0][ar] = a4.x; As[ac + 1][ar] = a4.y;
        As[ac + 2][ar] = a4.z; As[ac + 3][ar] = a4.w;
        float4 p4 = *(const float4*)(Pm + (size_t)pc * H_DIM + k0 + pk);
        Bs[pk + 0][pc] = p4.x; Bs[pk + 1][pc] = p4.y;
        Bs[pk + 2][pc] = p4.z; Bs[pk + 3][pc] = p4.w;
        __syncthreads();
#pragma unroll
        for (int kk = 0; kk < 16; kk++) {
            float4 a = *(const float4*)&As[kk][ty * 4];
            float4 b = *(const float4*)&Bs[kk][tx * 4];
            acc[0][0] += a.x * b.x; acc[0][1] += a.x * b.y;
            acc[0][2] += a.x * b.z; acc[0][3] += a.x * b.w;
            acc[1][0] += a.y * b.x; acc[1][1] += a.y * b.y;
            acc[1][2] += a.y * b.z; acc[1][3] += a.y * b.w;
            acc[2][0] += a.z * b.x; acc[2][1] += a.z * b.y;
            acc[2][2] += a.z * b.z; acc[2][3] += a.z * b.w;
            acc[3][0] += a.w * b.x; acc[3][1] += a.w * b.y;
            acc[3][2] += a.w * b.z; acc[3][3] += a.w * b.w;
        }
        __syncthreads();
    }
#pragma unroll
    for (int i = 0; i < 4; i++) {
#pragma unroll
        for (int j = 0; j < 4; j++) {
            int r = row0 + ty * 4 + i, c = tx * 4 + j;
            float d2 = g_hh[r] + g_pp[c] - 2.f * acc[i][j];
            d2 = fmaxf(d2, 0.f);
            // IEEE division to mirror the reference's (-cost)/tau exactly
            g_M[(size_t)r * K_PROT + c] = __fdiv_rn(-d2, 0.05f);
        }
    }
}

// ---------------- deterministic stable counting sort by joint type ---------
__global__ void sortk(const int* __restrict__ jt)
{
    __shared__ unsigned short hist[TYPES][256];
    __shared__ int cnt_s[TYPES], base[TYPES];
    int tid = threadIdx.x;
    for (int i = tid; i < TYPES * 256; i += 256) (&hist[0][0])[i] = 0;
    __syncthreads();
    int n0 = tid * 32;
    for (int j = 0; j < 32; j++) { int t = jt[n0 + j]; hist[t][tid]++; }
    __syncthreads();
    if (tid < TYPES) {
        int s = 0;
        for (int c = 0; c < 256; c++) s += hist[tid][c];
        cnt_s[tid] = s;
    }
    __syncthreads();
    if (tid == 0) {
        int b = 0;
        for (int t = 0; t < TYPES; t++) {
            base[t] = b; g_offs[t] = b; g_cnt[t] = cnt_s[t]; b += cnt_s[t];
        }
    }
    __syncthreads();
    if (tid < TYPES) {
        int run = base[tid];
        for (int c = 0; c < 256; c++) {
            int h = hist[tid][c];
            hist[tid][c] = (unsigned short)run;
            run += h;
        }
    }
    __syncthreads();
    for (int j = 0; j < 32; j++) {
        int n = n0 + j; int t = jt[n];
        int p = hist[t][tid]; hist[t][tid] = (unsigned short)(p + 1);
        g_perm[p] = n;
    }
}

// ---------------- cluster helpers ------------------------------------------
__device__ __forceinline__ unsigned smem_u32(const void* p) {
    return (unsigned)__cvta_generic_to_shared(p);
}
__device__ __forceinline__ unsigned mapa_u32(unsigned addr, unsigned rank) {
    unsigned r;
    asm("mapa.shared::cluster.u32 %0, %1, %2;" : "=r"(r) : "r"(addr), "r"(rank));
    return r;
}
__device__ __forceinline__ float ld_dsmem(unsigned addr) {
    float v;
    asm volatile("ld.shared::cluster.f32 %0, [%1];" : "=f"(v) : "r"(addr));
    return v;
}
__device__ __forceinline__ void cluster_sync_asm() {
    asm volatile("barrier.cluster.arrive.aligned;" ::: "memory");
    asm volatile("barrier.cluster.wait.aligned;" ::: "memory");
}

// ---------------- Sinkhorn: 17 independent problems, 8-CTA clusters --------
__global__ __cluster_dims__(CLUSTER, 1, 1) void sinkhorn_kernel()
{
    __shared__ float sM[ROWS_MAX][K_PROT + 1];
    __shared__ float sU[ROWS_MAX];
    __shared__ float sV[K_PROT];
    __shared__ float sPm[2][K_PROT];
    __shared__ float sPs[2][K_PROT];

    int tid = threadIdx.x, lane = tid & 31, warp = tid >> 5;
    int t = blockIdx.x / CLUSTER;
    unsigned rank;
    asm("mov.u32 %0, %%cluster_ctarank;" : "=r"(rank));

    int cnt = g_cnt[t], off = g_offs[t];
    int per = (cnt + CLUSTER - 1) / CLUSTER;
    if (per > ROWS_MAX) per = ROWS_MAX;   // safety cap (never hit in practice)
    int r0 = (int)rank * per;
    int nr = cnt - r0; if (nr < 0) nr = 0; if (nr > per) nr = per;

    for (int idx = tid; idx < nr * K_PROT; idx += 256) {
        int r = idx >> 6, c = idx & 63;
        sM[r][c] = g_M[(size_t)g_perm[off + r0 + r] * K_PROT + c];
    }
    if (tid < K_PROT) sV[tid] = 0.f;

    unsigned pm_rem[2][CLUSTER], ps_rem[2][CLUSTER];
    {
        unsigned pm0 = smem_u32(&sPm[0][0]), pm1 = smem_u32(&sPm[1][0]);
        unsigned ps0 = smem_u32(&sPs[0][0]), ps1 = smem_u32(&sPs[1][0]);
#pragma unroll
        for (int rk = 0; rk < CLUSTER; rk++) {
            pm_rem[0][rk] = mapa_u32(pm0, rk); pm_rem[1][rk] = mapa_u32(pm1, rk);
            ps_rem[0][rk] = mapa_u32(ps0, rk); ps_rem[1][rk] = mapa_u32(ps1, rk);
        }
    }

    int buf = 0;
    for (int it = 0; it < ITERS; it++) {
        __syncthreads();
        // --- row update: log_u = -LSE_k(M + v) ---
        for (int r = warp; r < nr; r += 8) {
            float x0 = sM[r][lane] + sV[lane];
            float x1 = sM[r][lane + 32] + sV[lane + 32];
            float m = fmaxf(x0, x1);
#pragma unroll
            for (int o = 16; o; o >>= 1)
                m = fmaxf(m, __shfl_xor_sync(0xffffffffu, m, o));
            float s = __expf(x0 - m) + __expf(x1 - m);
#pragma unroll
            for (int o = 16; o; o >>= 1)
                s += __shfl_xor_sync(0xffffffffu, s, o);
            if (lane == 0) sU[r] = -(m + __logf(s));
        }
        __syncthreads();
        // --- column partial LSE over local rows ---
        for (int c = warp; c < K_PROT; c += 8) {
            float m = -3.4e38f;
            for (int r = lane; r < nr; r += 32)
                m = fmaxf(m, sM[r][c] + sU[r]);
#pragma unroll
            for (int o = 16; o; o >>= 1)
                m = fmaxf(m, __shfl_xor_sync(0xffffffffu, m, o));
            float s = 0.f;
            for (int r = lane; r < nr; r += 32)
                s += __expf(sM[r][c] + sU[r] - m);
#pragma unroll
            for (int o = 16; o; o >>= 1)
                s += __shfl_xor_sync(0xffffffffu, s, o);
            if (lane == 0) { sPm[buf][c] = m; sPs[buf][c] = s; }
        }
        cluster_sync_asm();
        // --- combine partials (replicated per CTA): v = -klf * log_s ---
        if (tid < K_PROT) {
            int c = tid;
            float pm[CLUSTER], ps[CLUSTER];
#pragma unroll
            for (int rk = 0; rk < CLUSTER; rk++) {
                pm[rk] = ld_dsmem(pm_rem[buf][rk] + (unsigned)(c * 4));
                ps[rk] = ld_dsmem(ps_rem[buf][rk] + (unsigned)(c * 4));
            }
            float mx = pm[0];
#pragma unroll
            for (int rk = 1; rk < CLUSTER; rk++) mx = fmaxf(mx, pm[rk]);
            float S = 0.f;
#pragma unroll
            for (int rk = 0; rk < CLUSTER; rk++)
                if (ps[rk] > 0.f) S += ps[rk] * __expf(pm[rk] - mx);
            sV[c] = -KLF * (mx + __logf(S));
        }
        buf ^= 1;
    }
    __syncthreads();
    for (int i = tid; i < nr; i += 256) g_u[g_perm[off + r0 + i]] = sU[i];
    if (rank == 0 && tid < K_PROT) g_v[t * K_PROT + tid] = sV[tid];
    cluster_sync_asm();   // keep DSMEM alive until all remote reads done
}

// ---------------- outputs ---------------------------------------------------
__global__ void zeroT(float4* __restrict__ T4, int n4)
{
    int i = blockIdx.x * blockDim.x + threadIdx.x;
    if (i < n4) T4[i] = make_float4(0.f, 0.f, 0.f, 0.f);
}

__global__ void fill_out(const int* __restrict__ jt,
                         float* __restrict__ logits, float* __restrict__ T)
{
    int idx = blockIdx.x * blockDim.x + threadIdx.x;
    if (idx >= N_ROWS * K_PROT) return;
    int n = idx >> 6, k = idx & 63;
    int t = jt[n];
    float a = g_M[idx] + g_u[n] + g_v[t * K_PROT + k];
    float p = expf(a);
    if (T) T[(size_t)n * SLOTS + k * TYPES + t] = p;
    if (logits) logits[idx] = logf(p + 1e-8f);
}

// ---------------- launch -----------------------------------------------------
extern "C" void kernel_launch(void* const* d_in, const int* in_sizes, int n_in,
                              void* d_out, int out_size)
{
    const float* emb = (const float*)d_in[0];
    const int*   jt  = (const int*)d_in[1];
    const float* W1  = (const float*)d_in[2];
    const float* b1  = (const float*)d_in[3];
    const float* P   = (const float*)d_in[4];

    float* out = (float*)d_out;
    const long NK = (long)N_ROWS * K_PROT;
    const long NS = (long)N_ROWS * SLOTS;
    float* logits = nullptr; float* T = nullptr;
    if ((long)out_size >= NK + NS)      { logits = out; T = out + NK; }
    else if ((long)out_size >= NS)      { T = out; }
    else                                { logits = out; }

    gemm1_selu<<<dim3(H_DIM / 64, N_ROWS / 64), 256>>>(emb, W1, b1);
    rownorms<<<1032, 256>>>(P);
    gemm2_M<<<N_ROWS / 64, 256>>>(P);
    sortk<<<1, 256>>>(jt);
    sinkhorn_kernel<<<TYPES * CLUSTER, 256>>>();
    if (T) {
        int n4 = (int)(NS / 4);
        zeroT<<<(n4 + 255) / 256, 256>>>((float4*)T, n4);
    }
    fill_out<<<(N_ROWS * K_PROT + 255) / 256, 256>>>(jt, logits, T);
}

// round 3
// speedup vs baseline: 1.5260x; 1.5260x over previous
#include <cuda_runtime.h>
#include <cstdint>

#define N_ROWS 8192
#define D_IN   256
#define H_DIM  512
#define K_PROT 64
#define TYPES  17
#define SLOTS  (K_PROT*TYPES)
#define CLUSTER 8
#define ROWS_MAX 128
#define KLF (1.0f/1.05f)
#define ITERS 50

// ---------------- scratch (static device globals; no allocs allowed) -------
__device__ float g_h[N_ROWS*H_DIM];   // 16 MB
__device__ float g_M[N_ROWS*K_PROT];  // 2 MB : -d2/tau
__device__ int   g_perm[N_ROWS];
__device__ int   g_offs[TYPES];
__device__ int   g_cnt[TYPES];
__device__ float g_u[N_ROWS];
__device__ float g_v[SLOTS];          // [t*64 + k]

// ---------------- GEMM1: h = selu(emb @ W1 + b1) ---------------------------
__global__ void gemm1_selu(const float* __restrict__ A,  // [8192,256]
                           const float* __restrict__ B,  // [256,512]
                           const float* __restrict__ bias)
{
    __shared__ float As[16][68];
    __shared__ float Bs[16][68];
    int tid = threadIdx.x;
    int tx = tid & 15, ty = tid >> 4;
    int row0 = blockIdx.y * 64, col0 = blockIdx.x * 64;
    float acc[4][4];
#pragma unroll
    for (int i = 0; i < 4; i++)
#pragma unroll
        for (int j = 0; j < 4; j++) acc[i][j] = 0.f;

    int ar = tid >> 2, ac = (tid & 3) * 4;
    int br = tid >> 4, bc = (tid & 15) * 4;

    for (int k0 = 0; k0 < D_IN; k0 += 16) {
        float4 a4 = *(const float4*)(A + (size_t)(row0 + ar) * D_IN + k0 + ac);
        As[ac + 0][ar] = a4.x; As[ac + 1][ar] = a4.y;
        As[ac + 2][ar] = a4.z; As[ac + 3][ar] = a4.w;
        *(float4*)&Bs[br][bc] =
            *(const float4*)(B + (size_t)(k0 + br) * H_DIM + col0 + bc);
        __syncthreads();
#pragma unroll
        for (int kk = 0; kk < 16; kk++) {
            float4 a = *(const float4*)&As[kk][ty * 4];
            float4 b = *(const float4*)&Bs[kk][tx * 4];
            acc[0][0] += a.x * b.x; acc[0][1] += a.x * b.y;
            acc[0][2] += a.x * b.z; acc[0][3] += a.x * b.w;
            acc[1][0] += a.y * b.x; acc[1][1] += a.y * b.y;
            acc[1][2] += a.y * b.z; acc[1][3] += a.y * b.w;
            acc[2][0] += a.z * b.x; acc[2][1] += a.z * b.y;
            acc[2][2] += a.z * b.z; acc[2][3] += a.z * b.w;
            acc[3][0] += a.w * b.x; acc[3][1] += a.w * b.y;
            acc[3][2] += a.w * b.z; acc[3][3] += a.w * b.w;
        }
        __syncthreads();
    }
    const float LAM = 1.0507009873554805f, AL = 1.6732632423543772f;
#pragma unroll
    for (int i = 0; i < 4; i++) {
#pragma unroll
        for (int j = 0; j < 4; j++) {
            float x = acc[i][j] + bias[col0 + tx * 4 + j];
            float y = (x > 0.f) ? LAM * x : LAM * AL * expm1f(x);
            g_h[(size_t)(row0 + ty * 4 + i) * H_DIM + col0 + tx * 4 + j] = y;
        }
    }
}

// ---------------- GEMM2: M = -max(d2,0)/tau  (row/col norms fused) ---------
__global__ void gemm2_M(const float* __restrict__ Pm)  // [64,512]
{
    __shared__ float As[16][68];
    __shared__ float Bs[16][68];
    __shared__ float hhp[64][4];
    __shared__ float ppp[64][4];
    int tid = threadIdx.x;
    int tx = tid & 15, ty = tid >> 4;
    int row0 = blockIdx.x * 64;
    float acc[4][4];
#pragma unroll
    for (int i = 0; i < 4; i++)
#pragma unroll
        for (int j = 0; j < 4; j++) acc[i][j] = 0.f;

    int ar = tid >> 2, ac = (tid & 3) * 4;
    int pc = tid >> 2, pk = (tid & 3) * 4;
    float sa = 0.f, sp = 0.f;

    for (int k0 = 0; k0 < H_DIM; k0 += 16) {
        float4 a4 = *(const float4*)(g_h + (size_t)(row0 + ar) * H_DIM + k0 + ac);
        As[ac + 0][ar] = a4.x; As[ac + 1][ar] = a4.y;
        As[ac + 2][ar] = a4.z; As[ac + 3][ar] = a4.w;
        sa += a4.x * a4.x + a4.y * a4.y + a4.z * a4.z + a4.w * a4.w;
        float4 p4 = *(const float4*)(Pm + (size_t)pc * H_DIM + k0 + pk);
        Bs[pk + 0][pc] = p4.x; Bs[pk + 1][pc] = p4.y;
        Bs[pk + 2][pc] = p4.z; Bs[pk + 3][pc] = p4.w;
        sp += p4.x * p4.x + p4.y * p4.y + p4.z * p4.z + p4.w * p4.w;
        __syncthreads();
#pragma unroll
        for (int kk = 0; kk < 16; kk++) {
            float4 a = *(const float4*)&As[kk][ty * 4];
            float4 b = *(const float4*)&Bs[kk][tx * 4];
            acc[0][0] += a.x * b.x; acc[0][1] += a.x * b.y;
            acc[0][2] += a.x * b.z; acc[0][3] += a.x * b.w;
            acc[1][0] += a.y * b.x; acc[1][1] += a.y * b.y;
            acc[1][2] += a.y * b.z; acc[1][3] += a.y * b.w;
            acc[2][0] += a.z * b.x; acc[2][1] += a.z * b.y;
            acc[2][2] += a.z * b.z; acc[2][3] += a.z * b.w;
            acc[3][0] += a.w * b.x; acc[3][1] += a.w * b.y;
            acc[3][2] += a.w * b.z; acc[3][3] += a.w * b.w;
        }
        __syncthreads();
    }
    hhp[ar][tid & 3] = sa;
    ppp[pc][tid & 3] = sp;
    __syncthreads();
#pragma unroll
    for (int i = 0; i < 4; i++) {
        int rl = ty * 4 + i;
        float hh = hhp[rl][0] + hhp[rl][1] + hhp[rl][2] + hhp[rl][3];
#pragma unroll
        for (int j = 0; j < 4; j++) {
            int c = tx * 4 + j;
            float pp = ppp[c][0] + ppp[c][1] + ppp[c][2] + ppp[c][3];
            float d2 = hh + pp - 2.f * acc[i][j];
            d2 = fmaxf(d2, 0.f);
            // IEEE division to mirror the reference's (-cost)/tau exactly
            g_M[(size_t)(row0 + rl) * K_PROT + c] = __fdiv_rn(-d2, 0.05f);
        }
    }
}

// ---------------- deterministic stable counting sort by joint type ---------
__global__ void sortk(const int* __restrict__ jt)
{
    __shared__ unsigned short hist[TYPES][256];
    __shared__ int base[TYPES];
    __shared__ int cnt_s[TYPES];
    int tid = threadIdx.x, lane = tid & 31, warp = tid >> 5;

    for (int i = tid; i < TYPES * 256; i += 256) (&hist[0][0])[i] = 0;
    __syncthreads();

    // pass 1: per-thread counts (vectorized loads, 32 elems/thread)
    int4 v[8];
    const int4* jt4 = (const int4*)jt;
#pragma unroll
    for (int j = 0; j < 8; j++) v[j] = jt4[tid * 8 + j];
#pragma unroll
    for (int j = 0; j < 8; j++) {
        hist[v[j].x][tid]++; hist[v[j].y][tid]++;
        hist[v[j].z][tid]++; hist[v[j].w][tid]++;
    }
    __syncthreads();

    // pass 2: per-type exclusive prefix over the 256 thread-columns
    // warp w handles types w, w+8, w+16
    for (int t = warp; t < TYPES; t += 8) {
        int c[8], seg = 0;
#pragma unroll
        for (int i = 0; i < 8; i++) { c[i] = hist[t][lane * 8 + i]; seg += c[i]; }
        int x = seg;
#pragma unroll
        for (int o = 1; o < 32; o <<= 1) {
            int y = __shfl_up_sync(0xffffffffu, x, o);
            if (lane >= o) x += y;
        }
        int run = x - seg;                      // exclusive prefix of this lane's segment
#pragma unroll
        for (int i = 0; i < 8; i++) {
            hist[t][lane * 8 + i] = (unsigned short)run;
            run += c[i];
        }
        if (lane == 31) cnt_s[t] = x;           // total for type t
    }
    __syncthreads();
    if (tid == 0) {
        int b = 0;
        for (int t = 0; t < TYPES; t++) {
            base[t] = b; g_offs[t] = b; g_cnt[t] = cnt_s[t]; b += cnt_s[t];
        }
    }
    __syncthreads();

    // pass 3: stable scatter
#pragma unroll
    for (int j = 0; j < 8; j++) {
        int n0 = tid * 32 + j * 4;
        int t0 = v[j].x, t1 = v[j].y, t2 = v[j].z, t3 = v[j].w;
        int p;
        p = hist[t0][tid]; hist[t0][tid] = (unsigned short)(p + 1); g_perm[base[t0] + p] = n0 + 0;
        p = hist[t1][tid]; hist[t1][tid] = (unsigned short)(p + 1); g_perm[base[t1] + p] = n0 + 1;
        p = hist[t2][tid]; hist[t2][tid] = (unsigned short)(p + 1); g_perm[base[t2] + p] = n0 + 2;
        p = hist[t3][tid]; hist[t3][tid] = (unsigned short)(p + 1); g_perm[base[t3] + p] = n0 + 3;
    }
}

// ---------------- cluster helpers ------------------------------------------
__device__ __forceinline__ unsigned smem_u32(const void* p) {
    return (unsigned)__cvta_generic_to_shared(p);
}
__device__ __forceinline__ unsigned mapa_u32(unsigned addr, unsigned rank) {
    unsigned r;
    asm("mapa.shared::cluster.u32 %0, %1, %2;" : "=r"(r) : "r"(addr), "r"(rank));
    return r;
}
__device__ __forceinline__ float ld_dsmem(unsigned addr) {
    float v;
    asm volatile("ld.shared::cluster.f32 %0, [%1];" : "=f"(v) : "r"(addr));
    return v;
}
__device__ __forceinline__ void cluster_sync_asm() {
    asm volatile("barrier.cluster.arrive.aligned;" ::: "memory");
    asm volatile("barrier.cluster.wait.aligned;" ::: "memory");
}

// ---------------- Sinkhorn: 17 independent problems, 8-CTA clusters --------
// ILP x4: each warp reduces 4 rows (or 4 cols) concurrently so the 26-cycle
// SHFL and 16-cycle MUFU latencies overlap across independent chains.
__global__ __cluster_dims__(CLUSTER, 1, 1) void sinkhorn_kernel()
{
    __shared__ float sM[ROWS_MAX][K_PROT + 1];
    __shared__ float sU[ROWS_MAX];
    __shared__ float sV[K_PROT];
    __shared__ float sPm[2][K_PROT];
    __shared__ float sPs[2][K_PROT];

    int tid = threadIdx.x, lane = tid & 31, warp = tid >> 5;
    int t = blockIdx.x / CLUSTER;
    unsigned rank;
    asm("mov.u32 %0, %%cluster_ctarank;" : "=r"(rank));

    int cnt = g_cnt[t], off = g_offs[t];
    int per = (cnt + CLUSTER - 1) / CLUSTER;
    if (per > ROWS_MAX) per = ROWS_MAX;   // safety cap (never hit in practice)
    int r0 = (int)rank * per;
    int nr = cnt - r0; if (nr < 0) nr = 0; if (nr > per) nr = per;

    for (int idx = tid; idx < nr * K_PROT; idx += 256) {
        int r = idx >> 6, c = idx & 63;
        sM[r][c] = g_M[(size_t)g_perm[off + r0 + r] * K_PROT + c];
    }
    if (tid < K_PROT) sV[tid] = 0.f;

    unsigned pm_rem[2][CLUSTER], ps_rem[2][CLUSTER];
    {
        unsigned pm0 = smem_u32(&sPm[0][0]), pm1 = smem_u32(&sPm[1][0]);
        unsigned ps0 = smem_u32(&sPs[0][0]), ps1 = smem_u32(&sPs[1][0]);
#pragma unroll
        for (int rk = 0; rk < CLUSTER; rk++) {
            pm_rem[0][rk] = mapa_u32(pm0, rk); pm_rem[1][rk] = mapa_u32(pm1, rk);
            ps_rem[0][rk] = mapa_u32(ps0, rk); ps_rem[1][rk] = mapa_u32(ps1, rk);
        }
    }

    const float NEG = -3.4e38f;
    int buf = 0;
    for (int it = 0; it < ITERS; it++) {
        __syncthreads();
        // --- row update: log_u = -LSE_k(M + v), 4 rows per warp in flight ---
        for (int jb = 0; warp + jb * 8 < nr; jb += 4) {
            float x0[4], x1[4], m[4], s[4];
            int rr[4];
#pragma unroll
            for (int q = 0; q < 4; q++) {
                int r = warp + (jb + q) * 8;
                rr[q] = r;
                int ri = (r < ROWS_MAX) ? r : 0;
                x0[q] = sM[ri][lane] + sV[lane];
                x1[q] = sM[ri][lane + 32] + sV[lane + 32];
                m[q] = fmaxf(x0[q], x1[q]);
            }
#pragma unroll
            for (int o = 16; o; o >>= 1) {
#pragma unroll
                for (int q = 0; q < 4; q++)
                    m[q] = fmaxf(m[q], __shfl_xor_sync(0xffffffffu, m[q], o));
            }
#pragma unroll
            for (int q = 0; q < 4; q++)
                s[q] = __expf(x0[q] - m[q]) + __expf(x1[q] - m[q]);
#pragma unroll
            for (int o = 16; o; o >>= 1) {
#pragma unroll
                for (int q = 0; q < 4; q++)
                    s[q] += __shfl_xor_sync(0xffffffffu, s[q], o);
            }
            if (lane == 0) {
#pragma unroll
                for (int q = 0; q < 4; q++)
                    if (rr[q] < nr) sU[rr[q]] = -(m[q] + __logf(s[q]));
            }
        }
        __syncthreads();
        // --- column partial LSE over local rows, 4 cols per warp in flight ---
        {
            bool e0 = lane < nr, e1 = lane + 32 < nr, e2 = lane + 64 < nr;
            float u0 = e0 ? sU[lane] : 0.f;
            float u1 = e1 ? sU[lane + 32] : 0.f;
            float u2 = e2 ? sU[lane + 64] : 0.f;
#pragma unroll
            for (int jb = 0; jb < 8; jb += 4) {
                float y0[4], y1[4], y2[4], m[4], s[4];
#pragma unroll
                for (int q = 0; q < 4; q++) {
                    int c = warp + (jb + q) * 8;
                    y0[q] = e0 ? sM[lane][c] + u0 : NEG;
                    y1[q] = e1 ? sM[lane + 32][c] + u1 : NEG;
                    y2[q] = e2 ? sM[lane + 64][c] + u2 : NEG;
                    m[q] = fmaxf(fmaxf(y0[q], y1[q]), y2[q]);
                }
#pragma unroll
                for (int o = 16; o; o >>= 1) {
#pragma unroll
                    for (int q = 0; q < 4; q++)
                        m[q] = fmaxf(m[q], __shfl_xor_sync(0xffffffffu, m[q], o));
                }
#pragma unroll
                for (int q = 0; q < 4; q++) {
                    float a = e0 ? __expf(y0[q] - m[q]) : 0.f;
                    float b = e1 ? __expf(y1[q] - m[q]) : 0.f;
                    float cc = e2 ? __expf(y2[q] - m[q]) : 0.f;
                    s[q] = a + b + cc;
                }
#pragma unroll
                for (int o = 16; o; o >>= 1) {
#pragma unroll
                    for (int q = 0; q < 4; q++)
                        s[q] += __shfl_xor_sync(0xffffffffu, s[q], o);
                }
                if (lane == 0) {
#pragma unroll
                    for (int q = 0; q < 4; q++) {
                        int c = warp + (jb + q) * 8;
                        sPm[buf][c] = m[q]; sPs[buf][c] = s[q];
                    }
                }
            }
        }
        cluster_sync_asm();
        // --- combine partials (replicated per CTA): v = -klf * log_s ---
        if (tid < K_PROT) {
            int c = tid;
            float pm[CLUSTER], ps[CLUSTER];
#pragma unroll
            for (int rk = 0; rk < CLUSTER; rk++) {
                pm[rk] = ld_dsmem(pm_rem[buf][rk] + (unsigned)(c * 4));
                ps[rk] = ld_dsmem(ps_rem[buf][rk] + (unsigned)(c * 4));
            }
            float mx = pm[0];
#pragma unroll
            for (int rk = 1; rk < CLUSTER; rk++) mx = fmaxf(mx, pm[rk]);
            float S = 0.f;
#pragma unroll
            for (int rk = 0; rk < CLUSTER; rk++)
                if (ps[rk] > 0.f) S += ps[rk] * __expf(pm[rk] - mx);
            sV[c] = -KLF * (mx + __logf(S));
        }
        buf ^= 1;
    }
    __syncthreads();
    for (int i = tid; i < nr; i += 256) g_u[g_perm[off + r0 + i]] = sU[i];
    if (rank == 0 && tid < K_PROT) g_v[t * K_PROT + tid] = sV[tid];
    cluster_sync_asm();   // keep DSMEM alive until all remote reads done
}

// ---------------- outputs ---------------------------------------------------
__global__ void zeroT(float4* __restrict__ T4, int n4)
{
    int i = blockIdx.x * blockDim.x + threadIdx.x;
    if (i < n4) T4[i] = make_float4(0.f, 0.f, 0.f, 0.f);
}

__global__ void fill_out(const int* __restrict__ jt,
                         float* __restrict__ logits, float* __restrict__ T)
{
    int idx = blockIdx.x * blockDim.x + threadIdx.x;
    if (idx >= N_ROWS * K_PROT) return;
    int n = idx >> 6, k = idx & 63;
    int t = jt[n];
    float a = g_M[idx] + g_u[n] + g_v[t * K_PROT + k];
    float p = expf(a);
    if (T) T[(size_t)n * SLOTS + k * TYPES + t] = p;
    if (logits) logits[idx] = logf(p + 1e-8f);
}

// ---------------- launch -----------------------------------------------------
extern "C" void kernel_launch(void* const* d_in, const int* in_sizes, int n_in,
                              void* d_out, int out_size)
{
    const float* emb = (const float*)d_in[0];
    const int*   jt  = (const int*)d_in[1];
    const float* W1  = (const float*)d_in[2];
    const float* b1  = (const float*)d_in[3];
    const float* P   = (const float*)d_in[4];

    float* out = (float*)d_out;
    const long NK = (long)N_ROWS * K_PROT;
    const long NS = (long)N_ROWS * SLOTS;
    float* logits = nullptr; float* T = nullptr;
    if ((long)out_size >= NK + NS)      { logits = out; T = out + NK; }
    else if ((long)out_size >= NS)      { T = out; }
    else                                { logits = out; }

    gemm1_selu<<<dim3(H_DIM / 64, N_ROWS / 64), 256>>>(emb, W1, b1);
    sortk<<<1, 256>>>(jt);
    gemm2_M<<<N_ROWS / 64, 256>>>(P);
    sinkhorn_kernel<<<TYPES * CLUSTER, 256>>>();
    if (T) {
        int n4 = (int)(NS / 4);
        zeroT<<<(n4 + 255) / 256, 256>>>((float4*)T, n4);
    }
    fill_out<<<(N_ROWS * K_PROT + 255) / 256, 256>>>(jt, logits, T);
}

// round 4
// speedup vs baseline: 1.7938x; 1.1755x over previous
#include <cuda_runtime.h>
#include <cstdint>

#define N_ROWS 8192
#define D_IN   256
#define H_DIM  512
#define K_PROT 64
#define TYPES  17
#define SLOTS  (K_PROT*TYPES)
#define CLUSTER 8
#define ROWS_MAX 128
#define KLF (1.0f/1.05f)
#define ITERS 50
#define NEGBIG (-1.0e30f)

// smem layout (floats) for sinkhorn
#define SM_STRIDE  68
#define SMT_STRIDE 132
#define OFF_SM   0
#define OFF_SMT  (ROWS_MAX*SM_STRIDE)                 // 8704
#define OFF_SU   (OFF_SMT + K_PROT*SMT_STRIDE)        // 17152
#define OFF_SV   (OFF_SU + ROWS_MAX)                  // 17280
#define OFF_PM   (OFF_SV + K_PROT)                    // 17344
#define OFF_PS   (OFF_PM + 2*K_PROT)                  // 17472
#define SMEM_FLOATS (OFF_PS + 2*K_PROT)               // 17600
#define SMEM_BYTES  (SMEM_FLOATS*4)                   // 70400

// ---------------- scratch (static device globals; no allocs allowed) -------
__device__ float g_h[N_ROWS*H_DIM];   // 16 MB
__device__ float g_M[N_ROWS*K_PROT];  // 2 MB : -d2/tau
__device__ int   g_perm[N_ROWS];
__device__ int   g_offs[TYPES];
__device__ int   g_cnt[TYPES];
__device__ float g_u[N_ROWS];
__device__ float g_v[SLOTS];          // [t*64 + k]

// ---------------- GEMM1: h = selu(emb @ W1 + b1) ---------------------------
__global__ void gemm1_selu(const float* __restrict__ A,  // [8192,256]
                           const float* __restrict__ B,  // [256,512]
                           const float* __restrict__ bias)
{
    __shared__ float As[16][68];
    __shared__ float Bs[16][68];
    int tid = threadIdx.x;
    int tx = tid & 15, ty = tid >> 4;
    int row0 = blockIdx.y * 64, col0 = blockIdx.x * 64;
    float acc[4][4];
#pragma unroll
    for (int i = 0; i < 4; i++)
#pragma unroll
        for (int j = 0; j < 4; j++) acc[i][j] = 0.f;

    int ar = tid >> 2, ac = (tid & 3) * 4;
    int br = tid >> 4, bc = (tid & 15) * 4;

    for (int k0 = 0; k0 < D_IN; k0 += 16) {
        float4 a4 = *(const float4*)(A + (size_t)(row0 + ar) * D_IN + k0 + ac);
        As[ac + 0][ar] = a4.x; As[ac + 1][ar] = a4.y;
        As[ac + 2][ar] = a4.z; As[ac + 3][ar] = a4.w;
        *(float4*)&Bs[br][bc] =
            *(const float4*)(B + (size_t)(k0 + br) * H_DIM + col0 + bc);
        __syncthreads();
#pragma unroll
        for (int kk = 0; kk < 16; kk++) {
            float4 a = *(const float4*)&As[kk][ty * 4];
            float4 b = *(const float4*)&Bs[kk][tx * 4];
            acc[0][0] += a.x * b.x; acc[0][1] += a.x * b.y;
            acc[0][2] += a.x * b.z; acc[0][3] += a.x * b.w;
            acc[1][0] += a.y * b.x; acc[1][1] += a.y * b.y;
            acc[1][2] += a.y * b.z; acc[1][3] += a.y * b.w;
            acc[2][0] += a.z * b.x; acc[2][1] += a.z * b.y;
            acc[2][2] += a.z * b.z; acc[2][3] += a.z * b.w;
            acc[3][0] += a.w * b.x; acc[3][1] += a.w * b.y;
            acc[3][2] += a.w * b.z; acc[3][3] += a.w * b.w;
        }
        __syncthreads();
    }
    const float LAM = 1.0507009873554805f, AL = 1.6732632423543772f;
#pragma unroll
    for (int i = 0; i < 4; i++) {
#pragma unroll
        for (int j = 0; j < 4; j++) {
            float x = acc[i][j] + bias[col0 + tx * 4 + j];
            float y = (x > 0.f) ? LAM * x : LAM * AL * expm1f(x);
            g_h[(size_t)(row0 + ty * 4 + i) * H_DIM + col0 + tx * 4 + j] = y;
        }
    }
}

// ---------------- GEMM2: M = -max(d2,0)/tau  (row/col norms fused) ---------
__global__ void gemm2_M(const float* __restrict__ Pm)  // [64,512]
{
    __shared__ float As[16][68];
    __shared__ float Bs[16][68];
    __shared__ float hhp[64][4];
    __shared__ float ppp[64][4];
    int tid = threadIdx.x;
    int tx = tid & 15, ty = tid >> 4;
    int row0 = blockIdx.x * 64;
    float acc[4][4];
#pragma unroll
    for (int i = 0; i < 4; i++)
#pragma unroll
        for (int j = 0; j < 4; j++) acc[i][j] = 0.f;

    int ar = tid >> 2, ac = (tid & 3) * 4;
    int pc = tid >> 2, pk = (tid & 3) * 4;
    float sa = 0.f, sp = 0.f;

    for (int k0 = 0; k0 < H_DIM; k0 += 16) {
        float4 a4 = *(const float4*)(g_h + (size_t)(row0 + ar) * H_DIM + k0 + ac);
        As[ac + 0][ar] = a4.x; As[ac + 1][ar] = a4.y;
        As[ac + 2][ar] = a4.z; As[ac + 3][ar] = a4.w;
        sa += a4.x * a4.x + a4.y * a4.y + a4.z * a4.z + a4.w * a4.w;
        float4 p4 = *(const float4*)(Pm + (size_t)pc * H_DIM + k0 + pk);
        Bs[pk + 0][pc] = p4.x; Bs[pk + 1][pc] = p4.y;
        Bs[pk + 2][pc] = p4.z; Bs[pk + 3][pc] = p4.w;
        sp += p4.x * p4.x + p4.y * p4.y + p4.z * p4.z + p4.w * p4.w;
        __syncthreads();
#pragma unroll
        for (int kk = 0; kk < 16; kk++) {
            float4 a = *(const float4*)&As[kk][ty * 4];
            float4 b = *(const float4*)&Bs[kk][tx * 4];
            acc[0][0] += a.x * b.x; acc[0][1] += a.x * b.y;
            acc[0][2] += a.x * b.z; acc[0][3] += a.x * b.w;
            acc[1][0] += a.y * b.x; acc[1][1] += a.y * b.y;
            acc[1][2] += a.y * b.z; acc[1][3] += a.y * b.w;
            acc[2][0] += a.z * b.x; acc[2][1] += a.z * b.y;
            acc[2][2] += a.z * b.z; acc[2][3] += a.z * b.w;
            acc[3][0] += a.w * b.x; acc[3][1] += a.w * b.y;
            acc[3][2] += a.w * b.z; acc[3][3] += a.w * b.w;
        }
        __syncthreads();
    }
    hhp[ar][tid & 3] = sa;
    ppp[pc][tid & 3] = sp;
    __syncthreads();
#pragma unroll
    for (int i = 0; i < 4; i++) {
        int rl = ty * 4 + i;
        float hh = hhp[rl][0] + hhp[rl][1] + hhp[rl][2] + hhp[rl][3];
#pragma unroll
        for (int j = 0; j < 4; j++) {
            int c = tx * 4 + j;
            float pp = ppp[c][0] + ppp[c][1] + ppp[c][2] + ppp[c][3];
            float d2 = hh + pp - 2.f * acc[i][j];
            d2 = fmaxf(d2, 0.f);
            // IEEE division to mirror the reference's (-cost)/tau exactly
            g_M[(size_t)(row0 + rl) * K_PROT + c] = __fdiv_rn(-d2, 0.05f);
        }
    }
}

// ---------------- deterministic stable counting sort by joint type ---------
__global__ void sortk(const int* __restrict__ jt)
{
    __shared__ unsigned short hist[TYPES][256];
    __shared__ int base[TYPES];
    __shared__ int cnt_s[TYPES];
    int tid = threadIdx.x, lane = tid & 31, warp = tid >> 5;

    for (int i = tid; i < TYPES * 256; i += 256) (&hist[0][0])[i] = 0;
    __syncthreads();

    int4 v[8];
    const int4* jt4 = (const int4*)jt;
#pragma unroll
    for (int j = 0; j < 8; j++) v[j] = jt4[tid * 8 + j];
#pragma unroll
    for (int j = 0; j < 8; j++) {
        hist[v[j].x][tid]++; hist[v[j].y][tid]++;
        hist[v[j].z][tid]++; hist[v[j].w][tid]++;
    }
    __syncthreads();

    for (int t = warp; t < TYPES; t += 8) {
        int c[8], seg = 0;
#pragma unroll
        for (int i = 0; i < 8; i++) { c[i] = hist[t][lane * 8 + i]; seg += c[i]; }
        int x = seg;
#pragma unroll
        for (int o = 1; o < 32; o <<= 1) {
            int y = __shfl_up_sync(0xffffffffu, x, o);
            if (lane >= o) x += y;
        }
        int run = x - seg;
#pragma unroll
        for (int i = 0; i < 8; i++) {
            hist[t][lane * 8 + i] = (unsigned short)run;
            run += c[i];
        }
        if (lane == 31) cnt_s[t] = x;
    }
    __syncthreads();
    if (tid == 0) {
        int b = 0;
        for (int t = 0; t < TYPES; t++) {
            base[t] = b; g_offs[t] = b; g_cnt[t] = cnt_s[t]; b += cnt_s[t];
        }
    }
    __syncthreads();

#pragma unroll
    for (int j = 0; j < 8; j++) {
        int n0 = tid * 32 + j * 4;
        int t0 = v[j].x, t1 = v[j].y, t2 = v[j].z, t3 = v[j].w;
        int p;
        p = hist[t0][tid]; hist[t0][tid] = (unsigned short)(p + 1); g_perm[base[t0] + p] = n0 + 0;
        p = hist[t1][tid]; hist[t1][tid] = (unsigned short)(p + 1); g_perm[base[t1] + p] = n0 + 1;
        p = hist[t2][tid]; hist[t2][tid] = (unsigned short)(p + 1); g_perm[base[t2] + p] = n0 + 2;
        p = hist[t3][tid]; hist[t3][tid] = (unsigned short)(p + 1); g_perm[base[t3] + p] = n0 + 3;
    }
}

// ---------------- cluster helpers ------------------------------------------
__device__ __forceinline__ unsigned smem_u32(const void* p) {
    return (unsigned)__cvta_generic_to_shared(p);
}
__device__ __forceinline__ unsigned mapa_u32(unsigned addr, unsigned rank) {
    unsigned r;
    asm("mapa.shared::cluster.u32 %0, %1, %2;" : "=r"(r) : "r"(addr), "r"(rank));
    return r;
}
__device__ __forceinline__ float ld_dsmem(unsigned addr) {
    float v;
    asm volatile("ld.shared::cluster.f32 %0, [%1];" : "=f"(v) : "r"(addr));
    return v;
}
__device__ __forceinline__ void cluster_sync_asm() {
    asm volatile("barrier.cluster.arrive.aligned;" ::: "memory");
    asm volatile("barrier.cluster.wait.aligned;" ::: "memory");
}

// ---------------- Sinkhorn: 17 independent problems, 8-CTA clusters --------
// 4 threads per row/col; 16-element serial register reductions (float4 loads)
// + 2-level shfl within 4-lane groups. Cuts SHFL warp-ops ~20x vs warp-wide
// butterflies.
__global__ __cluster_dims__(CLUSTER, 1, 1) void sinkhorn_kernel()
{
    extern __shared__ float smem[];
    float* sM  = smem + OFF_SM;    // [ROWS_MAX][SM_STRIDE]
    float* sMt = smem + OFF_SMT;   // [K_PROT][SMT_STRIDE]
    float* sU  = smem + OFF_SU;    // [ROWS_MAX]
    float* sV  = smem + OFF_SV;    // [K_PROT]
    float* sPm = smem + OFF_PM;    // [2][K_PROT]
    float* sPs = smem + OFF_PS;    // [2][K_PROT]

    int tid = threadIdx.x;
    int t = blockIdx.x / CLUSTER;
    unsigned rank;
    asm("mov.u32 %0, %%cluster_ctarank;" : "=r"(rank));

    int cnt = g_cnt[t], off = g_offs[t];
    int per = (cnt + CLUSTER - 1) / CLUSTER;
    if (per > ROWS_MAX) per = ROWS_MAX;
    int r0 = (int)rank * per;
    int nr = cnt - r0; if (nr < 0) nr = 0; if (nr > per) nr = per;

    // load tile (row-major + transposed copy)
    for (int idx = tid; idx < nr * 16; idx += 256) {
        int r = idx >> 4, c4 = (idx & 15) * 4;
        float4 v = *(const float4*)(g_M + (size_t)g_perm[off + r0 + r] * K_PROT + c4);
        *(float4*)(sM + r * SM_STRIDE + c4) = v;
        sMt[(c4 + 0) * SMT_STRIDE + r] = v.x;
        sMt[(c4 + 1) * SMT_STRIDE + r] = v.y;
        sMt[(c4 + 2) * SMT_STRIDE + r] = v.z;
        sMt[(c4 + 3) * SMT_STRIDE + r] = v.w;
    }
    // pad rows [nr, ROWS_MAX) with NEGBIG in sMt and sU
    for (int idx = tid; idx < (ROWS_MAX - nr) * K_PROT; idx += 256) {
        int r = nr + idx / K_PROT, c = idx % K_PROT;
        sMt[c * SMT_STRIDE + r] = NEGBIG;
    }
    for (int r = nr + tid; r < ROWS_MAX; r += 256) sU[r] = NEGBIG;
    if (tid < K_PROT) sV[tid] = 0.f;

    unsigned pm_rem[2][CLUSTER], ps_rem[2][CLUSTER];
    {
        unsigned pm0 = smem_u32(sPm), pm1 = smem_u32(sPm + K_PROT);
        unsigned ps0 = smem_u32(sPs), ps1 = smem_u32(sPs + K_PROT);
#pragma unroll
        for (int rk = 0; rk < CLUSTER; rk++) {
            pm_rem[0][rk] = mapa_u32(pm0, rk); pm_rem[1][rk] = mapa_u32(pm1, rk);
            ps_rem[0][rk] = mapa_u32(ps0, rk); ps_rem[1][rk] = mapa_u32(ps1, rk);
        }
    }

    int rhalf = tid >> 2;        // 0..63
    int seg = tid & 3;           // 0..3
    int chunk = (((nr + 3) >> 2) + 3) & ~3;   // rows per thread in col pass (mult of 4)

    int buf = 0;
    for (int it = 0; it < ITERS; it++) {
        __syncthreads();
        // ---- row pass: log_u[r] = -LSE_c(M[r,c] + v[c]);  4 threads/row ----
        for (int rb = 0; rb < nr; rb += 64) {
            int r = rb + rhalf;
            const float* Mr = sM + r * SM_STRIDE + seg * 16;
            const float* Vr = sV + seg * 16;
            float x[16];
#pragma unroll
            for (int j = 0; j < 4; j++) {
                float4 a = *(const float4*)(Mr + 4 * j);
                float4 b = *(const float4*)(Vr + 4 * j);
                x[4*j+0] = a.x + b.x; x[4*j+1] = a.y + b.y;
                x[4*j+2] = a.z + b.z; x[4*j+3] = a.w + b.w;
            }
            float m8[8];
#pragma unroll
            for (int j = 0; j < 8; j++) m8[j] = fmaxf(x[j], x[j + 8]);
            float m4a = fmaxf(m8[0], m8[4]), m4b = fmaxf(m8[1], m8[5]);
            float m4c = fmaxf(m8[2], m8[6]), m4d = fmaxf(m8[3], m8[7]);
            float m = fmaxf(fmaxf(m4a, m4b), fmaxf(m4c, m4d));
            m = fmaxf(m, __shfl_xor_sync(0xffffffffu, m, 1));
            m = fmaxf(m, __shfl_xor_sync(0xffffffffu, m, 2));
            float e0 = 0.f, e1 = 0.f, e2 = 0.f, e3 = 0.f;
#pragma unroll
            for (int j = 0; j < 4; j++) {
                e0 += __expf(x[4*j+0] - m); e1 += __expf(x[4*j+1] - m);
                e2 += __expf(x[4*j+2] - m); e3 += __expf(x[4*j+3] - m);
            }
            float s = (e0 + e1) + (e2 + e3);
            s += __shfl_xor_sync(0xffffffffu, s, 1);
            s += __shfl_xor_sync(0xffffffffu, s, 2);
            if (seg == 0 && r < nr) sU[r] = -(m + __logf(s));
        }
        __syncthreads();
        // ---- col pass: partial LSE_r(M[r,c] + u[r]);  4 threads/col -------
        {
            int c = rhalf;
            const float* Mc = sMt + c * SMT_STRIDE + seg * chunk;
            const float* Uc = sU + seg * chunk;
            float ma = NEGBIG, mb = NEGBIG, mc = NEGBIG, md = NEGBIG;
            for (int j = 0; j < chunk; j += 4) {
                float4 a = *(const float4*)(Mc + j);
                float4 u = *(const float4*)(Uc + j);
                ma = fmaxf(ma, a.x + u.x); mb = fmaxf(mb, a.y + u.y);
                mc = fmaxf(mc, a.z + u.z); md = fmaxf(md, a.w + u.w);
            }
            float m = fmaxf(fmaxf(ma, mb), fmaxf(mc, md));
            m = fmaxf(m, __shfl_xor_sync(0xffffffffu, m, 1));
            m = fmaxf(m, __shfl_xor_sync(0xffffffffu, m, 2));
            float e0 = 0.f, e1 = 0.f, e2 = 0.f, e3 = 0.f;
            for (int j = 0; j < chunk; j += 4) {
                float4 a = *(const float4*)(Mc + j);
                float4 u = *(const float4*)(Uc + j);
                e0 += __expf(a.x + u.x - m); e1 += __expf(a.y + u.y - m);
                e2 += __expf(a.z + u.z - m); e3 += __expf(a.w + u.w - m);
            }
            float s = (e0 + e1) + (e2 + e3);
            s += __shfl_xor_sync(0xffffffffu, s, 1);
            s += __shfl_xor_sync(0xffffffffu, s, 2);
            if (seg == 0) { sPm[buf * K_PROT + c] = m; sPs[buf * K_PROT + c] = s; }
        }
        cluster_sync_asm();
        // ---- combine partials across the cluster: v = -klf * log_s --------
        if (tid < K_PROT) {
            int c = tid;
            float pm[CLUSTER], ps[CLUSTER];
#pragma unroll
            for (int rk = 0; rk < CLUSTER; rk++) {
                pm[rk] = ld_dsmem(pm_rem[buf][rk] + (unsigned)(c * 4));
                ps[rk] = ld_dsmem(ps_rem[buf][rk] + (unsigned)(c * 4));
            }
            float mx = pm[0];
#pragma unroll
            for (int rk = 1; rk < CLUSTER; rk++) mx = fmaxf(mx, pm[rk]);
            float S = 0.f;
#pragma unroll
            for (int rk = 0; rk < CLUSTER; rk++)
                if (ps[rk] > 0.f) S += ps[rk] * __expf(pm[rk] - mx);
            sV[c] = -KLF * (mx + __logf(S));
        }
        buf ^= 1;
    }
    __syncthreads();
    for (int i = tid; i < nr; i += 256) g_u[g_perm[off + r0 + i]] = sU[i];
    if (rank == 0 && tid < K_PROT) g_v[t * K_PROT + tid] = sV[tid];
    cluster_sync_asm();   // keep DSMEM alive until all remote reads done
}

// ---------------- outputs ---------------------------------------------------
__global__ void zeroT(float4* __restrict__ T4, int n4)
{
    int i = blockIdx.x * blockDim.x + threadIdx.x;
    if (i < n4) T4[i] = make_float4(0.f, 0.f, 0.f, 0.f);
}

__global__ void fill_out(const int* __restrict__ jt,
                         float* __restrict__ logits, float* __restrict__ T)
{
    int idx = blockIdx.x * blockDim.x + threadIdx.x;
    if (idx >= N_ROWS * K_PROT) return;
    int n = idx >> 6, k = idx & 63;
    int t = jt[n];
    float a = g_M[idx] + g_u[n] + g_v[t * K_PROT + k];
    float p = __expf(a);
    if (T) T[(size_t)n * SLOTS + k * TYPES + t] = p;
    if (logits) logits[idx] = __logf(p + 1e-8f);
}

// ---------------- launch -----------------------------------------------------
extern "C" void kernel_launch(void* const* d_in, const int* in_sizes, int n_in,
                              void* d_out, int out_size)
{
    const float* emb = (const float*)d_in[0];
    const int*   jt  = (const int*)d_in[1];
    const float* W1  = (const float*)d_in[2];
    const float* b1  = (const float*)d_in[3];
    const float* P   = (const float*)d_in[4];

    float* out = (float*)d_out;
    const long NK = (long)N_ROWS * K_PROT;
    const long NS = (long)N_ROWS * SLOTS;
    float* logits = nullptr; float* T = nullptr;
    if ((long)out_size >= NK + NS)      { logits = out; T = out + NK; }
    else if ((long)out_size >= NS)      { T = out; }
    else                                { logits = out; }

    static int smem_set = 0;
    if (!smem_set) {
        cudaFuncSetAttribute(sinkhorn_kernel,
                             cudaFuncAttributeMaxDynamicSharedMemorySize,
                             SMEM_BYTES);
        smem_set = 1;
    }

    gemm1_selu<<<dim3(H_DIM / 64, N_ROWS / 64), 256>>>(emb, W1, b1);
    sortk<<<1, 256>>>(jt);
    gemm2_M<<<N_ROWS / 64, 256>>>(P);
    sinkhorn_kernel<<<TYPES * CLUSTER, 256, SMEM_BYTES>>>();
    if (T) {
        int n4 = (int)(NS / 4);
        zeroT<<<(n4 + 255) / 256, 256>>>((float4*)T, n4);
    }
    fill_out<<<(N_ROWS * K_PROT + 255) / 256, 256>>>(jt, logits, T);
}